// round 5
// baseline (speedup 1.0000x reference)
#include <cuda_runtime.h>
#include <cuda_fp16.h>

#define D 128
#define MAX_N 100000
#define MBLK 64            // rows of x per GEMM block
#define PADH 136           // smem row stride in halves
#define EPB 1024           // edges per scatter block
#define CPB 4              // chains per block
#define CLEN (EPB / CPB)   // 256 edges per chain

// support = x@W + b, stored fp16 (25.6 MB)
__device__ __half g_support_h[(size_t)MAX_N * D];
// W transposed + converted to fp16: Wt[n][k]
__device__ __half g_Wt_h[D * D];

// ---------------------------------------------------------------------------
// prep: Wt_h[n][k] = fp16(W[k][n])
// ---------------------------------------------------------------------------
__global__ void prep_kernel(const float* __restrict__ W, __half* __restrict__ Wt) {
    int i = blockIdx.x * blockDim.x + threadIdx.x;
    if (i < D * D) {
        int k = i >> 7, n = i & 127;
        Wt[n * D + k] = __float2half(W[i]);
    }
}

__device__ __forceinline__ void mma_f16(float d[4], unsigned a0, unsigned a1,
                                        unsigned a2, unsigned a3,
                                        unsigned b0, unsigned b1) {
    asm volatile(
        "mma.sync.aligned.m16n8k16.row.col.f32.f16.f16.f32 "
        "{%0,%1,%2,%3}, {%4,%5,%6,%7}, {%8,%9}, {%0,%1,%2,%3};"
        : "+f"(d[0]), "+f"(d[1]), "+f"(d[2]), "+f"(d[3])
        : "r"(a0), "r"(a1), "r"(a2), "r"(a3), "r"(b0), "r"(b1));
}

// ---------------------------------------------------------------------------
// GEMM: support = fp16(x@W + b) via fp16 mma m16n8k16. Also zeroes its rows
// of `out`. (Memory-floor bound; unchanged from R4.)
// ---------------------------------------------------------------------------
__global__ void __launch_bounds__(256) gemm_mma_kernel(
        const float* __restrict__ x,
        const __half* __restrict__ Wt,
        const float* __restrict__ b,
        __half* __restrict__ sup,
        float* __restrict__ out, int N) {
    extern __shared__ __half smem[];
    __half* sX = smem;                 // 64  x PADH halves
    __half* sW = smem + MBLK * PADH;   // 128 x PADH halves ([n][k])

    const int tid  = threadIdx.x;
    const int lane = tid & 31;
    const int w    = tid >> 5;
    const int wm   = w & 3;
    const int wn   = w >> 2;
    const int g    = lane >> 2;
    const int tig  = lane & 3;

    const int row0 = blockIdx.x * MBLK;

    const uint4* Wv = (const uint4*)Wt;
    #pragma unroll
    for (int i = tid; i < 128 * 16; i += 256) {
        int r = i >> 4, c = i & 15;
        *(uint4*)(sW + r * PADH + c * 8) = Wv[i];
    }
    const float4* xv = (const float4*)x;
    #pragma unroll
    for (int i = tid; i < MBLK * 32; i += 256) {
        int r = i >> 5, c = i & 31;
        float4 v = make_float4(0.f, 0.f, 0.f, 0.f);
        if (row0 + r < N) v = xv[(size_t)(row0 + r) * 32 + c];
        __half2 h0 = __floats2half2_rn(v.x, v.y);
        __half2 h1 = __floats2half2_rn(v.z, v.w);
        uint2 p = make_uint2(*(unsigned*)&h0, *(unsigned*)&h1);
        *(uint2*)(sX + r * PADH + c * 4) = p;
    }
    __syncthreads();

    float acc[8][4];
    #pragma unroll
    for (int t = 0; t < 8; t++)
        #pragma unroll
        for (int j = 0; j < 4; j++) acc[t][j] = 0.f;

    const int ar0 = wm * 16 + g;
    const int ar1 = ar0 + 8;

    #pragma unroll
    for (int k0 = 0; k0 < D; k0 += 16) {
        unsigned a0 = *(const unsigned*)(sX + ar0 * PADH + k0 + 2 * tig);
        unsigned a1 = *(const unsigned*)(sX + ar1 * PADH + k0 + 2 * tig);
        unsigned a2 = *(const unsigned*)(sX + ar0 * PADH + k0 + 2 * tig + 8);
        unsigned a3 = *(const unsigned*)(sX + ar1 * PADH + k0 + 2 * tig + 8);
        #pragma unroll
        for (int t = 0; t < 8; t++) {
            int n0 = wn * 64 + t * 8;
            unsigned b0 = *(const unsigned*)(sW + (n0 + g) * PADH + k0 + 2 * tig);
            unsigned b1 = *(const unsigned*)(sW + (n0 + g) * PADH + k0 + 2 * tig + 8);
            mma_f16(acc[t], a0, a1, a2, a3, b0, b1);
        }
    }

    const int gr0 = row0 + wm * 16 + g;
    const int gr1 = gr0 + 8;
    #pragma unroll
    for (int t = 0; t < 8; t++) {
        int col = wn * 64 + t * 8 + 2 * tig;
        float bx = b[col], by = b[col + 1];
        if (gr0 < N) {
            __half2 h = __floats2half2_rn(acc[t][0] + bx, acc[t][1] + by);
            *(__half2*)(sup + (size_t)gr0 * D + col) = h;
        }
        if (gr1 < N) {
            __half2 h = __floats2half2_rn(acc[t][2] + bx, acc[t][3] + by);
            *(__half2*)(sup + (size_t)gr1 * D + col) = h;
        }
    }

    const float4 z4 = make_float4(0.f, 0.f, 0.f, 0.f);
    float4* outv = (float4*)out;
    #pragma unroll
    for (int i = tid; i < MBLK * 32; i += 256) {
        int r = i >> 5;
        if (row0 + r < N) outv[(size_t)(row0 + r) * 32 + (i & 31)] = z4;
    }
}

// ---------------------------------------------------------------------------
// Scatter: out[dst] += w_e * support[src]  (fp16 gather, fp32 accumulate).
// int4-packed metadata (1 LDS.128/edge). Run-accumulate; interior runs
// (sole chip-wide writer, since edge_dst is globally sorted) flush with one
// STG.128; only chain-boundary dsts use atomics.
// ---------------------------------------------------------------------------
__global__ void __launch_bounds__(128) scatter_kernel(
        const __half* __restrict__ sup,
        const float* __restrict__ ew,
        const int* __restrict__ esrc,
        const int* __restrict__ edst,
        float* __restrict__ out, int E) {
    __shared__ int4 s_m[EPB + 1];      // (src, dst, w_bits, pad)

    const int base = blockIdx.x * EPB;
    const int n = min(EPB, E - base);

    for (int i = threadIdx.x; i < n; i += 128) {
        s_m[i] = make_int4(esrc[base + i], edst[base + i],
                           __float_as_int(ew[base + i]), 0);
    }
    __syncthreads();
    // Sentinels: same (valid) src/dst as last real edge, weight 0.
    for (int i = n + (int)threadIdx.x; i <= EPB; i += 128) {
        int4 t = s_m[n - 1];
        t.z = 0;                       // w = 0.0f
        s_m[i] = t;
    }
    __syncthreads();

    const int chain = threadIdx.x >> 5;
    const int lane  = threadIdx.x & 31;
    const int cbeg  = chain * CLEN;

    // Chain-boundary destinations (may have writers in other chains/blocks)
    const int first_dst = s_m[cbeg].y;
    const int last_dst  = s_m[cbeg + CLEN - 1].y;

    const uint2* supv = (const uint2*)sup;

    int4  m = s_m[cbeg];
    uint2 u = supv[(size_t)m.x * 32 + lane];

    float4 acc = make_float4(0.f, 0.f, 0.f, 0.f);

    #pragma unroll 8
    for (int j = 0; j < CLEN; j++) {
        const int e = cbeg + j;
        int4  mn = s_m[e + 1];
        uint2 un = supv[(size_t)mn.x * 32 + lane];

        const float w = __int_as_float(m.z);
        float2 f0 = __half22float2(*(__half2*)(&u.x));
        float2 f1 = __half22float2(*(__half2*)(&u.y));
        acc.x += w * f0.x; acc.y += w * f0.y;
        acc.z += w * f1.x; acc.w += w * f1.y;

        if ((j == CLEN - 1) | (m.y != mn.y)) {
            float* o = out + (size_t)m.y * D + lane * 4;
            if ((m.y != first_dst) & (m.y != last_dst)) {
                *(float4*)o = acc;            // sole writer: plain store
            } else {
                atomicAdd(o + 0, acc.x);
                atomicAdd(o + 1, acc.y);
                atomicAdd(o + 2, acc.z);
                atomicAdd(o + 3, acc.w);
            }
            acc = make_float4(0.f, 0.f, 0.f, 0.f);
        }
        m = mn; u = un;
    }
}

extern "C" void kernel_launch(void* const* d_in, const int* in_sizes, int n_in,
                              void* d_out, int out_size) {
    const float* x    = (const float*)d_in[0];
    const float* W    = (const float*)d_in[1];
    const float* b    = (const float*)d_in[2];
    const float* ew   = (const float*)d_in[3];
    const int*   esrc = (const int*)d_in[4];
    const int*   edst = (const int*)d_in[5];
    float* out = (float*)d_out;

    const int N = in_sizes[0] / D;
    const int E = in_sizes[3];

    __half* sup = nullptr;
    cudaGetSymbolAddress((void**)&sup, g_support_h);
    __half* Wt = nullptr;
    cudaGetSymbolAddress((void**)&Wt, g_Wt_h);

    prep_kernel<<<(D * D + 255) / 256, 256>>>(W, Wt);

    const int gemm_smem = (MBLK * PADH + D * PADH) * (int)sizeof(__half); // ~52 KB
    cudaFuncSetAttribute(gemm_mma_kernel, cudaFuncAttributeMaxDynamicSharedMemorySize, gemm_smem);

    const int gemm_blocks = (N + MBLK - 1) / MBLK;
    gemm_mma_kernel<<<gemm_blocks, 256, gemm_smem>>>(x, Wt, b, sup, out, N);

    const int scat_blocks = (E + EPB - 1) / EPB;
    scatter_kernel<<<scat_blocks, 128>>>(sup, ew, esrc, edst, out, E);
}